// round 3
// baseline (speedup 1.0000x reference)
#include <cuda_runtime.h>

#define A_    3
#define T_    64
#define B_    256
#define ENTO_ 2048
#define EM_   1024
#define IN_   4096
#define N_    (A_ * EM_)     /* 3072 */
#define MROWS (T_ * B_)      /* 16384 */

// ---- device scratch (allowed: __device__ globals, no allocation) ----
__device__ float g_WentoT[ENTO_ * N_];      // [k=2048][n=3072]  ento projection weights, K-major
__device__ float g_WrecT [N_ * N_];         // [k=3072][n=3072]  merged recurrent weights, K-major
__device__ float g_V[2][B_ * N_];           // ping-pong voltages, [b][n] with n = a*1024+e

// ------------------------------------------------------------------
// Prep kernels
// ------------------------------------------------------------------
__global__ void build_wento_t(const float* __restrict__ w_ih) {
    int idx = blockIdx.x * blockDim.x + threadIdx.x;
    if (idx >= ENTO_ * N_) return;
    int k = idx / N_;
    int n = idx - k * N_;
    int a = n >> 10, e = n & 1023;
    g_WentoT[idx] = w_ih[(size_t)(a * EM_ + e) * IN_ + k];
}

__global__ void build_wrec_t(const float* __restrict__ w_ih,
                             const float* __restrict__ w_hh) {
    int idx = blockIdx.x * blockDim.x + threadIdx.x;
    if (idx >= N_ * N_) return;
    int k = idx / N_;
    int n = idx - k * N_;
    int j = k >> 10, m = k & 1023;
    int a = n >> 10, e = n & 1023;
    float v;
    if (j == a) {
        v = w_hh[(size_t)(a * EM_ + e) * EM_ + m];
    } else {
        int pos = j - (j > a ? 1 : 0);   // position of attr j in the "others" list of attr a
        v = w_ih[(size_t)(a * EM_ + e) * IN_ + ENTO_ + pos * EM_ + m];
    }
    g_WrecT[idx] = v;
}

__global__ void init_v(const float* __restrict__ v0) {
    int idx = blockIdx.x * blockDim.x + threadIdx.x;
    if (idx >= B_ * N_) return;
    int b = idx / N_;
    int k = idx - b * N_;
    int j = k >> 10, m = k & 1023;
    g_V[0][idx] = v0[(size_t)(j * B_ + b) * EM_ + m];
}

// ------------------------------------------------------------------
// Phase 1: ento projection GEMM  C[16384,3072] = ento[16384,2048] @ WentoT[2048,3072]
// Chunked-double accumulation: fp32 FMA within a 16-k chunk, folded into
// double accumulators (fp64 pipe runs concurrently, ~free).
// 64x64x16 tile, 256 threads, 4x4 per thread.
// Writes straight into d_out at [((t*3+a)*256+b)*1024+e].
// ------------------------------------------------------------------
__global__ __launch_bounds__(256) void phase1_gemm(const float* __restrict__ Amat,
                                                   float* __restrict__ out) {
    __shared__ float As[16][64];
    __shared__ float Bs[16][64];
    const int m0 = blockIdx.x * 64;
    const int n0 = blockIdx.y * 64;
    const int tid = threadIdx.x;
    const int tx = tid & 15, ty = tid >> 4;

    double dacc[4][4];
#pragma unroll
    for (int i = 0; i < 4; ++i)
#pragma unroll
        for (int j = 0; j < 4; ++j) dacc[i][j] = 0.0;

    const int arow = tid >> 2, akq = (tid & 3) * 4;
    const int bkr  = tid >> 4, bc  = (tid & 15) * 4;
    const float* Ap = Amat + (size_t)(m0 + arow) * ENTO_ + akq;
    const float* Bp = g_WentoT + (size_t)bkr * N_ + n0 + bc;

    for (int k0 = 0; k0 < ENTO_; k0 += 16) {
        float4 a4 = *(const float4*)Ap;  Ap += 16;
        As[akq + 0][arow] = a4.x;
        As[akq + 1][arow] = a4.y;
        As[akq + 2][arow] = a4.z;
        As[akq + 3][arow] = a4.w;
        *(float4*)&Bs[bkr][bc] = *(const float4*)Bp;  Bp += (size_t)16 * N_;
        __syncthreads();

        float facc[4][4];
#pragma unroll
        for (int i = 0; i < 4; ++i)
#pragma unroll
            for (int j = 0; j < 4; ++j) facc[i][j] = 0.f;
#pragma unroll
        for (int k = 0; k < 16; ++k) {
            float4 a = *(const float4*)&As[k][ty * 4];
            float4 b = *(const float4*)&Bs[k][tx * 4];
            float ar[4] = {a.x, a.y, a.z, a.w};
            float br[4] = {b.x, b.y, b.z, b.w};
#pragma unroll
            for (int i = 0; i < 4; ++i)
#pragma unroll
                for (int j = 0; j < 4; ++j) facc[i][j] += ar[i] * br[j];
        }
#pragma unroll
        for (int i = 0; i < 4; ++i)
#pragma unroll
            for (int j = 0; j < 4; ++j) dacc[i][j] += (double)facc[i][j];
        __syncthreads();
    }

#pragma unroll
    for (int i = 0; i < 4; ++i) {
        int row = m0 + ty * 4 + i;
        int t = row >> 8, b = row & 255;
        int col = n0 + tx * 4;                    // 4 cols stay within one attribute
        int a = col >> 10, e = col & 1023;
        float4 w = make_float4((float)dacc[i][0], (float)dacc[i][1],
                               (float)dacc[i][2], (float)dacc[i][3]);
        *(float4*)&out[((size_t)((t * 3 + a) * 256 + b)) * 1024 + e] = w;
    }
}

// ------------------------------------------------------------------
// Phase 2 step:  Vnext = clip( Vin @ WrecT + U_t + clip(Vin) )
// Chunked-double accumulation; final combine + clip in double, one rounding.
// 64x64x16 tile, 256 threads, 4x4 per thread, grid (4, 48) = 192 blocks.
// ------------------------------------------------------------------
__global__ __launch_bounds__(256) void step_gemm(int par, float* __restrict__ outT) {
    const float* __restrict__ Vin  = g_V[par];
    float* __restrict__       Vout = g_V[par ^ 1];

    __shared__ float As[16][64];
    __shared__ float Bs[16][64];
    const int m0 = blockIdx.x * 64;
    const int n0 = blockIdx.y * 64;
    const int tid = threadIdx.x;
    const int tx = tid & 15, ty = tid >> 4;

    double dacc[4][4];
#pragma unroll
    for (int i = 0; i < 4; ++i)
#pragma unroll
        for (int j = 0; j < 4; ++j) dacc[i][j] = 0.0;

    const int arow = tid >> 2, akq = (tid & 3) * 4;
    const int bkr  = tid >> 4, bc  = (tid & 15) * 4;
    const float* Ap = Vin + (size_t)(m0 + arow) * N_ + akq;
    const float* Bp = g_WrecT + (size_t)bkr * N_ + n0 + bc;

    for (int k0 = 0; k0 < N_; k0 += 16) {
        float4 a4 = *(const float4*)Ap;  Ap += 16;
        As[akq + 0][arow] = a4.x;
        As[akq + 1][arow] = a4.y;
        As[akq + 2][arow] = a4.z;
        As[akq + 3][arow] = a4.w;
        *(float4*)&Bs[bkr][bc] = *(const float4*)Bp;  Bp += (size_t)16 * N_;
        __syncthreads();

        float facc[4][4];
#pragma unroll
        for (int i = 0; i < 4; ++i)
#pragma unroll
            for (int j = 0; j < 4; ++j) facc[i][j] = 0.f;
#pragma unroll
        for (int k = 0; k < 16; ++k) {
            float4 a = *(const float4*)&As[k][ty * 4];
            float4 b = *(const float4*)&Bs[k][tx * 4];
            float ar[4] = {a.x, a.y, a.z, a.w};
            float br[4] = {b.x, b.y, b.z, b.w};
#pragma unroll
            for (int i = 0; i < 4; ++i)
#pragma unroll
                for (int j = 0; j < 4; ++j) facc[i][j] += ar[i] * br[j];
        }
#pragma unroll
        for (int i = 0; i < 4; ++i)
#pragma unroll
            for (int j = 0; j < 4; ++j) dacc[i][j] += (double)facc[i][j];
        __syncthreads();
    }

#pragma unroll
    for (int i = 0; i < 4; ++i) {
        int bb = m0 + ty * 4 + i;
        int n  = n0 + tx * 4;               // 4 consecutive cols within one attribute
        int a  = n >> 10, e = n & 1023;
        float4 vv = *(const float4*)&Vin[(size_t)bb * N_ + n];
        size_t oidx = ((size_t)(a * 256 + bb)) * 1024 + e;
        float4 u = *(const float4*)&outT[oidx];
        double vc0 = fmin(1.0, fmax(-1.0, (double)vv.x));
        double vc1 = fmin(1.0, fmax(-1.0, (double)vv.y));
        double vc2 = fmin(1.0, fmax(-1.0, (double)vv.z));
        double vc3 = fmin(1.0, fmax(-1.0, (double)vv.w));
        float4 r;
        r.x = (float)fmin(1.0, fmax(-1.0, dacc[i][0] + (double)u.x + vc0));
        r.y = (float)fmin(1.0, fmax(-1.0, dacc[i][1] + (double)u.y + vc1));
        r.z = (float)fmin(1.0, fmax(-1.0, dacc[i][2] + (double)u.z + vc2));
        r.w = (float)fmin(1.0, fmax(-1.0, dacc[i][3] + (double)u.w + vc3));
        *(float4*)&outT[oidx] = r;
        *(float4*)&Vout[(size_t)bb * N_ + n] = r;
    }
}

// ------------------------------------------------------------------
extern "C" void kernel_launch(void* const* d_in, const int* in_sizes, int n_in,
                              void* d_out, int out_size) {
    (void)in_sizes; (void)n_in; (void)out_size;
    const float* ento = (const float*)d_in[0];   // [T,B,ENTO]
    const float* v0   = (const float*)d_in[1];   // [A,B,EM]
    const float* w_ih = (const float*)d_in[2];   // [A,EM,IN]
    const float* w_hh = (const float*)d_in[3];   // [A,EM,EM]
    float* out = (float*)d_out;                  // [T,A,B,EM]

    build_wento_t<<<(ENTO_ * N_ + 255) / 256, 256>>>(w_ih);
    build_wrec_t <<<(N_ * N_   + 255) / 256, 256>>>(w_ih, w_hh);
    init_v       <<<(B_ * N_   + 255) / 256, 256>>>(v0);

    phase1_gemm<<<dim3(MROWS / 64, N_ / 64), 256>>>(ento, out);

    for (int t = 0; t < T_; ++t) {
        float* outT = out + (size_t)t * A_ * B_ * EM_;
        step_gemm<<<dim3(B_ / 64, N_ / 64), 256>>>(t & 1, outT);
    }
}

// round 8
// speedup vs baseline: 5.9373x; 5.9373x over previous
#include <cuda_runtime.h>
#include <cuda_bf16.h>
#include <cstdint>
#include <cstddef>

#define A_    3
#define T_    64
#define B_    256
#define ENTO_ 2048
#define EM_   1024
#define IN_   4096
#define N_    3072
#define MROWS 16384

// ---------------- device scratch (static globals; no allocation) ----------------
__device__ __nv_bfloat16 g_EntoS [3][(size_t)MROWS * ENTO_];  // ento bf16 splits [row][k]
__device__ __nv_bfloat16 g_WentoS[3][(size_t)N_ * ENTO_];     // W_ento splits   [n][k]
__device__ __nv_bfloat16 g_WrecS [3][(size_t)N_ * N_];        // merged W splits [n][k]
__device__ __nv_bfloat16 g_VS[2][3][B_ * N_];                 // V splits, ping-pong [b][n]
__device__ float         g_V [2][B_ * N_];                    // V fp32, ping-pong  [b][n]

// ---------------- helpers ----------------
__device__ __forceinline__ uint32_t smem_u32(const void* p) {
    uint32_t a;
    asm("{ .reg .u64 t; cvta.to.shared.u64 t, %1; cvt.u32.u64 %0, t; }" : "=r"(a) : "l"(p));
    return a;
}
__device__ __forceinline__ void split3(float f, __nv_bfloat16& h, __nv_bfloat16& m,
                                       __nv_bfloat16& l) {
    h = __float2bfloat16(f);
    float r = f - __bfloat162float(h);
    m = __float2bfloat16(r);
    r = r - __bfloat162float(m);
    l = __float2bfloat16(r);
}

#define LDSM4(r0, r1, r2, r3, addr) \
    asm volatile("ldmatrix.sync.aligned.m8n8.x4.shared.b16 {%0,%1,%2,%3}, [%4];" \
                 : "=r"(r0), "=r"(r1), "=r"(r2), "=r"(r3) : "r"(addr))

#define MMA16816(d, a, b) \
    asm volatile("mma.sync.aligned.m16n8k16.row.col.f32.bf16.bf16.f32 " \
                 "{%0,%1,%2,%3}, {%4,%5,%6,%7}, {%8,%9}, {%0,%1,%2,%3};" \
                 : "+f"((d)[0]), "+f"((d)[1]), "+f"((d)[2]), "+f"((d)[3]) \
                 : "r"((a)[0]), "r"((a)[1]), "r"((a)[2]), "r"((a)[3]), \
                   "r"((b)[0]), "r"((b)[1]))

#define CPASYNC16(dst, src) \
    asm volatile("cp.async.cg.shared.global [%0], [%1], 16;" :: "r"(dst), "l"(src))

// ---------------- prep (split) kernels ----------------
__global__ void split_ento(const float* __restrict__ ento) {
    int k = blockIdx.x * 256 + threadIdx.x;
    size_t idx = (size_t)blockIdx.y * ENTO_ + k;
    __nv_bfloat16 h, m, l; split3(ento[idx], h, m, l);
    g_EntoS[0][idx] = h; g_EntoS[1][idx] = m; g_EntoS[2][idx] = l;
}
__global__ void split_wento(const float* __restrict__ w_ih) {
    int k = blockIdx.x * 256 + threadIdx.x;
    int n = blockIdx.y;
    float f = w_ih[(size_t)n * IN_ + k];
    __nv_bfloat16 h, m, l; split3(f, h, m, l);
    size_t idx = (size_t)n * ENTO_ + k;
    g_WentoS[0][idx] = h; g_WentoS[1][idx] = m; g_WentoS[2][idx] = l;
}
__global__ void split_wrec(const float* __restrict__ w_ih, const float* __restrict__ w_hh) {
    int k = blockIdx.x * 256 + threadIdx.x;
    int n = blockIdx.y;
    int j = k >> 10, m_ = k & 1023;
    int a = n >> 10;
    float f;
    if (j == a) f = w_hh[(size_t)n * EM_ + m_];
    else {
        int pos = j - (j > a ? 1 : 0);
        f = w_ih[(size_t)n * IN_ + ENTO_ + pos * EM_ + m_];
    }
    __nv_bfloat16 h, m, l; split3(f, h, m, l);
    size_t idx = (size_t)n * N_ + k;
    g_WrecS[0][idx] = h; g_WrecS[1][idx] = m; g_WrecS[2][idx] = l;
}
__global__ void split_v0(const float* __restrict__ v0) {
    int n = blockIdx.x * 256 + threadIdx.x;
    int b = blockIdx.y;
    int j = n >> 10, m_ = n & 1023;
    float f = v0[((size_t)j * B_ + b) * EM_ + m_];
    g_V[0][b * N_ + n] = f;
    __nv_bfloat16 h, m, l; split3(f, h, m, l);
    g_VS[0][0][b * N_ + n] = h;
    g_VS[0][1][b * N_ + n] = m;
    g_VS[0][2][b * N_ + n] = l;
}

// ---------------- main 6-product bf16x3 mma.sync GEMM ----------------
// CTA tile 128x64, 8 warps (warp tile 32x32 = 2x4 m16n8k16).
// K staged 32 with cp.async double buffer. Smem rows padded to 80B.
// TRIPLE accumulators:
//   accH : hh product only, DRAINED into accS every 4 stages (bounds |accH|
//          so the tensor-core's truncating accumulate operates at small ulp)
//   accS : fp32 RNE fold of drained accH partials
//   accL : hm+mh+mm+hl+lh correction products (small magnitude, separate)
#define ASPLIT   10240           /* 128*80 */
#define BSPLIT    5120           /* 64*80  */
#define OFFB     30720           /* 3*ASPLIT */
#define BUFSZ    46080           /* OFFB + 3*BSPLIT */
#define SMEM_SZ  92160           /* 2 buffers */

template<int KDIM, bool STEP>
__global__ __launch_bounds__(256) void gemm6(int par, int t, float* __restrict__ dout) {
    constexpr int S = KDIM / 32;
    extern __shared__ char smem[];
    const uint32_t sb = smem_u32(smem);
    const int tid = threadIdx.x, wid = tid >> 5, lane = tid & 31;
    const int warp_m = wid & 3, warp_n = wid >> 2;
    const int n0 = blockIdx.x * 64;
    const int m0 = blockIdx.y * 128;

    const __nv_bfloat16* __restrict__ Asrc;
    const __nv_bfloat16* __restrict__ Bsrc;
    size_t Astride, Bstride;
    if (STEP) {
        Asrc = g_VS[par][0];  Astride = (size_t)B_ * N_;
        Bsrc = g_WrecS[0];    Bstride = (size_t)N_ * N_;
    } else {
        Asrc = g_EntoS[0];    Astride = (size_t)MROWS * ENTO_;
        Bsrc = g_WentoS[0];   Bstride = (size_t)N_ * ENTO_;
    }

    float accH[2][4][4], accL[2][4][4], accS[2][4][4];
#pragma unroll
    for (int i = 0; i < 2; ++i)
#pragma unroll
        for (int j = 0; j < 4; ++j)
#pragma unroll
            for (int q = 0; q < 4; ++q) {
                accH[i][j][q] = 0.f; accL[i][j][q] = 0.f; accS[i][j][q] = 0.f;
            }

    // ---- loader: 2304 16B units per 32-K chunk, 9 per thread ----
    auto loadChunk = [&](int s, uint32_t buf) {
        const int kb = s * 32;
#pragma unroll
        for (int i = 0; i < 9; ++i) {
            int u = tid + i * 256;
            const __nv_bfloat16* gp;
            uint32_t sa;
            if (u < 1536) {                    // A: sp(3) x row(128) x un(4)
                int sp = u >> 9, rem = u & 511, row = rem >> 2, un = rem & 3;
                gp = Asrc + sp * Astride + (size_t)(m0 + row) * KDIM + kb + un * 8;
                sa = buf + sp * ASPLIT + row * 80 + un * 16;
            } else {                           // B: sp(3) x row(64) x un(4)
                int v = u - 1536;
                int sp = v >> 8, rem = v & 255, row = rem >> 2, un = rem & 3;
                gp = Bsrc + sp * Bstride + (size_t)(n0 + row) * KDIM + kb + un * 8;
                sa = buf + OFFB + sp * BSPLIT + row * 80 + un * 16;
            }
            CPASYNC16(sa, gp);
        }
        asm volatile("cp.async.commit_group;" ::: "memory");
    };

    // per-thread ldmatrix byte offsets (within a split, before +kk*32)
    const int r16 = lane & 15, ahi = (lane >> 4) * 16;
    uint32_t aoff[2];
#pragma unroll
    for (int mt = 0; mt < 2; ++mt)
        aoff[mt] = (uint32_t)(warp_m * 32 + mt * 16 + r16) * 80 + ahi;
    const int bg = lane >> 3, bri = lane & 7;
    uint32_t boff[2];
#pragma unroll
    for (int p = 0; p < 2; ++p)
        boff[p] = (uint32_t)(warp_n * 32 + p * 16 + ((bg >> 1) << 3) + bri) * 80 + (bg & 1) * 16;

    loadChunk(0, sb);

    for (int s = 0; s < S; ++s) {
        if (s + 1 < S) {
            loadChunk(s + 1, sb + (uint32_t)((s + 1) & 1) * BUFSZ);
            asm volatile("cp.async.wait_group 1;" ::: "memory");
        } else {
            asm volatile("cp.async.wait_group 0;" ::: "memory");
        }
        __syncthreads();

        const uint32_t buf = sb + (uint32_t)(s & 1) * BUFSZ;
#pragma unroll
        for (int kk = 0; kk < 2; ++kk) {
            uint32_t af[3][2][4], bf[3][4][2];
#pragma unroll
            for (int sp = 0; sp < 3; ++sp) {
                uint32_t ab = buf + sp * ASPLIT + kk * 32;
#pragma unroll
                for (int mt = 0; mt < 2; ++mt)
                    LDSM4(af[sp][mt][0], af[sp][mt][1], af[sp][mt][2], af[sp][mt][3],
                          ab + aoff[mt]);
                uint32_t bb = buf + OFFB + sp * BSPLIT + kk * 32;
#pragma unroll
                for (int p = 0; p < 2; ++p)
                    LDSM4(bf[sp][2 * p][0], bf[sp][2 * p][1],
                          bf[sp][2 * p + 1][0], bf[sp][2 * p + 1][1],
                          bb + boff[p]);
            }
            // hh -> accH;  hm, mh, mm, hl, lh -> accL
#pragma unroll
            for (int mt = 0; mt < 2; ++mt)
#pragma unroll
                for (int nt = 0; nt < 4; ++nt) {
                    MMA16816(accH[mt][nt], af[0][mt], bf[0][nt]);
                    MMA16816(accL[mt][nt], af[0][mt], bf[1][nt]);
                    MMA16816(accL[mt][nt], af[1][mt], bf[0][nt]);
                    MMA16816(accL[mt][nt], af[1][mt], bf[1][nt]);
                    MMA16816(accL[mt][nt], af[0][mt], bf[2][nt]);
                    MMA16816(accL[mt][nt], af[2][mt], bf[0][nt]);
                }
        }
        __syncthreads();

        // drain accH -> accS every 4 stages (RNE FADD; keeps |accH| small so
        // the tensor core's truncating accumulate rounds at a small ulp)
        if ((s & 3) == 3) {
#pragma unroll
            for (int mt = 0; mt < 2; ++mt)
#pragma unroll
                for (int nt = 0; nt < 4; ++nt)
#pragma unroll
                    for (int q = 0; q < 4; ++q) {
                        accS[mt][nt][q] += accH[mt][nt][q];
                        accH[mt][nt][q] = 0.f;
                    }
        }
    }

    // ---- epilogue ----
    const int l4 = lane >> 2, l2 = (lane & 3) * 2;
#pragma unroll
    for (int mt = 0; mt < 2; ++mt) {
#pragma unroll
        for (int rh = 0; rh < 2; ++rh) {
            const int row = m0 + warp_m * 32 + mt * 16 + rh * 8 + l4;
#pragma unroll
            for (int nt = 0; nt < 4; ++nt) {
                const int c = n0 + warp_n * 32 + nt * 8 + l2;
                const int a = c >> 10, e = c & 1023;
                double x0 = (double)accS[mt][nt][rh * 2 + 0] + (double)accH[mt][nt][rh * 2 + 0]
                          + (double)accL[mt][nt][rh * 2 + 0];
                double x1 = (double)accS[mt][nt][rh * 2 + 1] + (double)accH[mt][nt][rh * 2 + 1]
                          + (double)accL[mt][nt][rh * 2 + 1];
                if (!STEP) {
                    const int tt = row >> 8, b = row & 255;
                    size_t oidx = ((size_t)((tt * 3 + a) * 256 + b)) * 1024 + e;
                    *(float2*)&dout[oidx] = make_float2((float)x0, (float)x1);
                } else {
                    const int b = row;    // batch
                    size_t oidx = ((size_t)((t * 3 + a) * 256 + b)) * 1024 + e;
                    float2 u = *(const float2*)&dout[oidx];
                    float2 v = *(const float2*)&g_V[par][(size_t)b * N_ + c];
                    float r0 = (float)fmin(1.0, fmax(-1.0, x0 + (double)u.x + (double)v.x));
                    float r1 = (float)fmin(1.0, fmax(-1.0, x1 + (double)u.y + (double)v.y));
                    *(float2*)&dout[oidx] = make_float2(r0, r1);
                    *(float2*)&g_V[par ^ 1][(size_t)b * N_ + c] = make_float2(r0, r1);
                    __nv_bfloat16 h0, mm0, l0, h1, mm1, l1;
                    split3(r0, h0, mm0, l0);
                    split3(r1, h1, mm1, l1);
                    *(__nv_bfloat162*)&g_VS[par ^ 1][0][(size_t)b * N_ + c] = __nv_bfloat162{h0, h1};
                    *(__nv_bfloat162*)&g_VS[par ^ 1][1][(size_t)b * N_ + c] = __nv_bfloat162{mm0, mm1};
                    *(__nv_bfloat162*)&g_VS[par ^ 1][2][(size_t)b * N_ + c] = __nv_bfloat162{l0, l1};
                }
            }
        }
    }
}

// ------------------------------------------------------------------
extern "C" void kernel_launch(void* const* d_in, const int* in_sizes, int n_in,
                              void* d_out, int out_size) {
    (void)in_sizes; (void)n_in; (void)out_size;
    const float* ento = (const float*)d_in[0];   // [T,B,ENTO]
    const float* v0   = (const float*)d_in[1];   // [A,B,EM]
    const float* w_ih = (const float*)d_in[2];   // [A,EM,IN]
    const float* w_hh = (const float*)d_in[3];   // [A,EM,EM]
    float* out = (float*)d_out;                  // [T,A,B,EM]

    cudaFuncSetAttribute(gemm6<ENTO_, false>, cudaFuncAttributeMaxDynamicSharedMemorySize, SMEM_SZ);
    cudaFuncSetAttribute(gemm6<N_, true>,     cudaFuncAttributeMaxDynamicSharedMemorySize, SMEM_SZ);

    split_ento <<<dim3(ENTO_ / 256, MROWS), 256>>>(ento);
    split_wento<<<dim3(ENTO_ / 256, N_),    256>>>(w_ih);
    split_wrec <<<dim3(N_ / 256, N_),       256>>>(w_ih, w_hh);
    split_v0   <<<dim3(N_ / 256, B_),       256>>>(v0);

    // Phase 1: U = ento @ Wento^T written straight into out
    gemm6<ENTO_, false><<<dim3(48, 128), 256, SMEM_SZ>>>(0, 0, out);

    // Phase 2: 64 recurrent steps (read U from out, overwrite with h)
    for (int t = 0; t < T_; ++t) {
        gemm6<N_, true><<<dim3(48, 2), 256, SMEM_SZ>>>(t & 1, t, out);
    }
}